// round 5
// baseline (speedup 1.0000x reference)
#include <cuda_runtime.h>
#include <cstdint>

// C = triu(A @ B), A,B upper-triangular fp32, N=4096.
// Round 5: TF32 mma.sync GEMM.
//   - cvt.rna.tf32 hoisted out of mainloop: cooperative in-smem conversion
//     pass per stage; fragments are raw LDS.32 -> MMA (no cvt in chain).
//   - A-fragment double buffering across k-steps.
//   - 128x128 tiles, split-K (atomic accumulate) for K>1024, longest-first.
//   - 3-stage cp.async pipeline, 2 CTAs/SM.

#define N_DIM 4096
#define BM 128
#define BN 128
#define BK 32
#define STAGES 3
#define NTHREADS 256
#define SPLIT_L 8

#define AP 36    // A smem row pitch (floats): conflict-free fragment loads
#define BP 136   // B smem row pitch (floats): conflict-free fragment loads
#define A_STAGE_FL (BM * AP)              // 4608
#define B_STAGE_FL (BK * BP)              // 4352
#define B_BASE_FL  (STAGES * A_STAGE_FL)  // 13824
#define SMEM_FL    (B_BASE_FL + STAGES * B_STAGE_FL)   // 26880 fl = 107520 B

#define MAX_PIECES 1024
__device__ int4 g_sched[MAX_PIECES];

__device__ __forceinline__ uint32_t smem_u32(const void* p) {
    uint32_t a;
    asm("{ .reg .u64 t; cvta.to.shared.u64 t, %1; cvt.u32.u64 %0, t; }" : "=r"(a) : "l"(p));
    return a;
}
__device__ __forceinline__ void cp_async16(uint32_t dst, const float* src) {
    asm volatile("cp.async.cg.shared.global [%0], [%1], 16;" :: "r"(dst), "l"(src));
}
__device__ __forceinline__ uint32_t ld_su32(const float* p) {
    uint32_t r;
    asm volatile("ld.shared.b32 %0, [%1];" : "=r"(r) : "l"(p));
    return r;
}
__device__ __forceinline__ float tf32_rna(float v) {
    asm("cvt.rna.tf32.f32 %0, %0;" : "+f"(v));
    return v;
}
__device__ __forceinline__ void red_add_f32(float* p, float v) {
    asm volatile("red.global.add.f32 [%0], %1;" :: "l"(p), "f"(v) : "memory");
}

__global__ __launch_bounds__(NTHREADS, 2)
void triu_gemm_tf32mma_kernel(const float* __restrict__ A,
                              const float* __restrict__ B,
                              float* __restrict__ C)
{
    extern __shared__ float sm[];
    const uint32_t smb = smem_u32(sm);

    const int tid  = threadIdx.x;
    const int wid  = tid >> 5;
    const int lane = tid & 31;
    const int qrow = lane >> 2;
    const int qcol = lane & 3;

    const int4 e  = g_sched[blockIdx.x];
    const int it    = e.x;
    const int jt    = e.y;
    const int k_beg = e.z;
    const int nch   = (e.w - e.z) / BK;
    const bool split = (jt - it + 1) > SPLIT_L;

    const int row0 = it * BM;
    const int col0 = jt * BN;

    const int wm = (wid & 1) * 64;
    const int wn = (wid >> 1) * 32;

    float acc[4][4][4];
#pragma unroll
    for (int i = 0; i < 4; i++)
#pragma unroll
        for (int j = 0; j < 4; j++)
#pragma unroll
            for (int r = 0; r < 4; r++) acc[i][j][r] = 0.0f;

    // cp.async thread mapping
    const int arow = tid >> 3;
    const int aseg = tid & 7;
    const int brow = tid >> 5;
    const int bseg = tid & 31;

    const float* Ag = A + (size_t)(row0 + arow) * N_DIM + aseg * 4;
    const float* Bg = B + (size_t)brow * N_DIM + col0 + bseg * 4;

#define LOAD_STAGE(s, kc)                                                        \
    do {                                                                         \
        const uint32_t abase = smb + ((s) * A_STAGE_FL) * 4;                     \
        const uint32_t bbase = smb + (B_BASE_FL + (s) * B_STAGE_FL) * 4;         \
        _Pragma("unroll")                                                        \
        for (int r = 0; r < 4; r++)                                             \
            cp_async16(abase + ((arow + r * 32) * AP + aseg * 4) * 4,            \
                       Ag + (size_t)(r * 32) * N_DIM + (kc));                    \
        _Pragma("unroll")                                                        \
        for (int r = 0; r < 4; r++)                                             \
            cp_async16(bbase + ((brow + r * 8) * BP + bseg * 4) * 4,             \
                       Bg + (size_t)((kc) + r * 8) * N_DIM);                     \
    } while (0)

#pragma unroll
    for (int s = 0; s < STAGES - 1; s++) {
        LOAD_STAGE(s, k_beg + s * BK);
        asm volatile("cp.async.commit_group;" ::: "memory");
    }

    for (int i = 0; i < nch; i++) {
        asm volatile("cp.async.wait_group %0;" :: "n"(STAGES - 2) : "memory");
        __syncthreads();

        const int s = i % STAGES;
        float* As = sm + s * A_STAGE_FL;
        float* Bs = sm + B_BASE_FL + s * B_STAGE_FL;

        // ---- In-smem tf32 rounding pass (vectorized, conflict-free) ----
        {
            float4* a4 = reinterpret_cast<float4*>(As);
#pragma unroll
            for (int p = tid; p < A_STAGE_FL / 4; p += NTHREADS) {
                float4 v = a4[p];
                v.x = tf32_rna(v.x); v.y = tf32_rna(v.y);
                v.z = tf32_rna(v.z); v.w = tf32_rna(v.w);
                a4[p] = v;
            }
            float4* b4 = reinterpret_cast<float4*>(Bs);
#pragma unroll
            for (int p = tid; p < B_STAGE_FL / 4; p += NTHREADS) {
                float4 v = b4[p];
                v.x = tf32_rna(v.x); v.y = tf32_rna(v.y);
                v.z = tf32_rna(v.z); v.w = tf32_rna(v.w);
                b4[p] = v;
            }
        }
        __syncthreads();

        // Issue next stage loads (after barrier: prev compute on that slot done).
        if (i + STAGES - 1 < nch)
            LOAD_STAGE((i + STAGES - 1) % STAGES, k_beg + (i + STAGES - 1) * BK);
        asm volatile("cp.async.commit_group;" ::: "memory");

        // ---- Mainloop: raw LDS fragments, A double-buffered ----
        const float* apb = As + (wm + qrow) * AP + qcol;
        const float* bpb = Bs + qcol * BP + wn + qrow;

        uint32_t af[2][4][4];
#pragma unroll
        for (int mt = 0; mt < 4; mt++) {
            const float* ap = apb + mt * 16 * AP;
            af[0][mt][0] = ld_su32(ap);
            af[0][mt][1] = ld_su32(ap + 8 * AP);
            af[0][mt][2] = ld_su32(ap + 4);
            af[0][mt][3] = ld_su32(ap + 8 * AP + 4);
        }

#pragma unroll
        for (int ks = 0; ks < BK / 8; ks++) {
            const int cur = ks & 1;
            uint32_t bf[4][2];
#pragma unroll
            for (int nt = 0; nt < 4; nt++) {
                const float* bp = bpb + ks * 8 * BP + nt * 8;
                bf[nt][0] = ld_su32(bp);
                bf[nt][1] = ld_su32(bp + 4 * BP);
            }
            if (ks < BK / 8 - 1) {
#pragma unroll
                for (int mt = 0; mt < 4; mt++) {
                    const float* ap = apb + mt * 16 * AP + (ks + 1) * 8;
                    af[cur ^ 1][mt][0] = ld_su32(ap);
                    af[cur ^ 1][mt][1] = ld_su32(ap + 8 * AP);
                    af[cur ^ 1][mt][2] = ld_su32(ap + 4);
                    af[cur ^ 1][mt][3] = ld_su32(ap + 8 * AP + 4);
                }
            }
#pragma unroll
            for (int mt = 0; mt < 4; mt++)
#pragma unroll
                for (int nt = 0; nt < 4; nt++) {
                    asm volatile(
                        "mma.sync.aligned.m16n8k8.row.col.f32.tf32.tf32.f32 "
                        "{%0,%1,%2,%3}, {%4,%5,%6,%7}, {%8,%9}, {%0,%1,%2,%3};"
                        : "+f"(acc[mt][nt][0]), "+f"(acc[mt][nt][1]),
                          "+f"(acc[mt][nt][2]), "+f"(acc[mt][nt][3])
                        : "r"(af[cur][mt][0]), "r"(af[cur][mt][1]),
                          "r"(af[cur][mt][2]), "r"(af[cur][mt][3]),
                          "r"(bf[nt][0]), "r"(bf[nt][1]));
                }
        }
        __syncthreads();
    }

    // ---- Epilogue ----
    if (split) {
#pragma unroll
        for (int mt = 0; mt < 4; mt++) {
            const int r_lo = row0 + wm + mt * 16 + qrow;
            float* crow_lo = C + (size_t)r_lo * N_DIM;
            float* crow_hi = crow_lo + (size_t)8 * N_DIM;
#pragma unroll
            for (int nt = 0; nt < 4; nt++) {
                const int gc = col0 + wn + nt * 8 + qcol * 2;
                red_add_f32(crow_lo + gc,     acc[mt][nt][0]);
                red_add_f32(crow_lo + gc + 1, acc[mt][nt][1]);
                red_add_f32(crow_hi + gc,     acc[mt][nt][2]);
                red_add_f32(crow_hi + gc + 1, acc[mt][nt][3]);
            }
        }
    } else {
#pragma unroll
        for (int mt = 0; mt < 4; mt++) {
            const int r_lo = row0 + wm + mt * 16 + qrow;
            const int r_hi = r_lo + 8;
            float* crow_lo = C + (size_t)r_lo * N_DIM;
            float* crow_hi = C + (size_t)r_hi * N_DIM;
#pragma unroll
            for (int nt = 0; nt < 4; nt++) {
                const int gc = col0 + wn + nt * 8 + qcol * 2;
                float2 v0, v1;
                v0.x = (gc + 0 >= r_lo) ? acc[mt][nt][0] : 0.0f;
                v0.y = (gc + 1 >= r_lo) ? acc[mt][nt][1] : 0.0f;
                v1.x = (gc + 0 >= r_hi) ? acc[mt][nt][2] : 0.0f;
                v1.y = (gc + 1 >= r_hi) ? acc[mt][nt][3] : 0.0f;
                *reinterpret_cast<float2*>(crow_lo + gc) = v0;
                *reinterpret_cast<float2*>(crow_hi + gc) = v1;
            }
        }
    }
}

extern "C" void kernel_launch(void* const* d_in, const int* in_sizes, int n_in,
                              void* d_out, int out_size) {
    const float* A = (const float*)d_in[0];
    const float* B = (const float*)d_in[1];
    float* C = (float*)d_out;

    static int4 h_sched[MAX_PIECES];
    int cnt = 0;
    for (int d = 31; d >= 0; d--) {
        const int len = d + 1;
        const int pieces = (len + SPLIT_L - 1) / SPLIT_L;
        for (int it = 0; it + d < 32; it++) {
            const int jt = it + d;
            for (int q = 0; q < pieces; q++) {
                const int c0 = it + (q * len) / pieces;
                const int c1 = it + ((q + 1) * len) / pieces;
                h_sched[cnt].x = it;
                h_sched[cnt].y = jt;
                h_sched[cnt].z = c0 * BM;
                h_sched[cnt].w = c1 * BM;
                cnt++;
            }
        }
    }

    cudaFuncSetAttribute(triu_gemm_tf32mma_kernel,
                         cudaFuncAttributeMaxDynamicSharedMemorySize,
                         SMEM_FL * sizeof(float));

    cudaMemcpyToSymbolAsync(g_sched, h_sched, cnt * sizeof(int4), 0,
                            cudaMemcpyHostToDevice, 0);
    cudaMemsetAsync(d_out, 0, (size_t)N_DIM * N_DIM * sizeof(float), 0);
    triu_gemm_tf32mma_kernel<<<cnt, NTHREADS, SMEM_FL * sizeof(float)>>>(A, B, C);
}

// round 6
// speedup vs baseline: 1.1048x; 1.1048x over previous
#include <cuda_runtime.h>
#include <cstdint>

// C = triu(A @ B), A,B upper-triangular fp32, N=4096.
// Round 6: TF32 mma.sync, 128x256 CTA tile / 64x64 warp tile (halves smem
// crossbar bytes per MMA), full A+B fragment double-buffering (breaks the
// LDS->MMA phase convoy), occ 1 (registers over occupancy), split-K >1024.

#define N_DIM 4096
#define BM 128
#define BN 256
#define BK 32
#define STAGES 3
#define NTHREADS 256
#define SPLIT_L 8     // max 128-chunks per piece

#define AP 36    // A smem pitch: bank (4*qrow+qcol) conflict-free
#define BP 264   // B smem pitch: 264%32=8 -> bank (8*qcol+qrow) conflict-free
#define A_STAGE_FL (BM * AP)               // 4608
#define B_STAGE_FL (BK * BP)               // 8448
#define B_BASE_FL  (STAGES * A_STAGE_FL)   // 13824
#define SMEM_FL    (B_BASE_FL + STAGES * B_STAGE_FL)   // 39168 fl = 156672 B

#define MAX_PIECES 1024
__device__ int4 g_sched[MAX_PIECES];

__device__ __forceinline__ uint32_t smem_u32(const void* p) {
    uint32_t a;
    asm("{ .reg .u64 t; cvta.to.shared.u64 t, %1; cvt.u32.u64 %0, t; }" : "=r"(a) : "l"(p));
    return a;
}
__device__ __forceinline__ void cp_async16(uint32_t dst, const float* src) {
    asm volatile("cp.async.cg.shared.global [%0], [%1], 16;" :: "r"(dst), "l"(src));
}
__device__ __forceinline__ uint32_t ld_tf32(const float* p) {
    uint32_t r;
    float v = *p;
    asm("cvt.rna.tf32.f32 %0, %1;" : "=r"(r) : "f"(v));
    return r;
}
__device__ __forceinline__ void red_add_f32(float* p, float v) {
    asm volatile("red.global.add.f32 [%0], %1;" :: "l"(p), "f"(v) : "memory");
}

__global__ __launch_bounds__(NTHREADS, 1)
void triu_gemm_tf32mma_kernel(const float* __restrict__ A,
                              const float* __restrict__ B,
                              float* __restrict__ C)
{
    extern __shared__ float sm[];
    const uint32_t smb = smem_u32(sm);

    const int tid  = threadIdx.x;
    const int wid  = tid >> 5;
    const int lane = tid & 31;
    const int qrow = lane >> 2;
    const int qcol = lane & 3;

    const int4 e  = g_sched[blockIdx.x];
    const int it    = e.x;
    const int jt    = e.y;
    const int k_beg = e.z;
    const int nch   = (e.w - e.z) / BK;
    const int split = e.w - e.z > SPLIT_L * 128 ? 0 : ((2 * jt + 2 - it) > SPLIT_L);

    const int row0 = it * BM;
    const int col0 = jt * BN;

    // Warps: 2 (m) x 4 (n); warp tile 64x64.
    const int wm = (wid & 1) * 64;
    const int wn = (wid >> 1) * 64;

    float acc[4][8][4];
#pragma unroll
    for (int i = 0; i < 4; i++)
#pragma unroll
        for (int j = 0; j < 8; j++)
#pragma unroll
            for (int r = 0; r < 4; r++) acc[i][j][r] = 0.0f;

    // cp.async thread mapping
    const int arow = tid >> 3;   // A: 128 rows x 8 segs; 4 reps of 32 rows
    const int aseg = tid & 7;
    const int brow = tid >> 6;   // B: 32 rows x 64 segs; 8 reps of 4 rows
    const int bseg = tid & 63;

    const float* Ag = A + (size_t)(row0 + arow) * N_DIM + aseg * 4;
    const float* Bg = B + (size_t)brow * N_DIM + col0 + bseg * 4;

#define LOAD_STAGE(s, kc)                                                        \
    do {                                                                         \
        const uint32_t abase = smb + ((s) * A_STAGE_FL) * 4;                     \
        const uint32_t bbase = smb + (B_BASE_FL + (s) * B_STAGE_FL) * 4;         \
        _Pragma("unroll")                                                        \
        for (int r = 0; r < 4; r++)                                             \
            cp_async16(abase + ((arow + r * 32) * AP + aseg * 4) * 4,            \
                       Ag + (size_t)(r * 32) * N_DIM + (kc));                    \
        _Pragma("unroll")                                                        \
        for (int r = 0; r < 8; r++)                                             \
            cp_async16(bbase + ((brow + r * 4) * BP + bseg * 4) * 4,             \
                       Bg + (size_t)((kc) + r * 4) * N_DIM);                     \
    } while (0)

#pragma unroll
    for (int s = 0; s < STAGES - 1; s++) {
        LOAD_STAGE(s, k_beg + s * BK);
        asm volatile("cp.async.commit_group;" ::: "memory");
    }

    for (int i = 0; i < nch; i++) {
        asm volatile("cp.async.wait_group %0;" :: "n"(STAGES - 2) : "memory");
        __syncthreads();

        if (i + STAGES - 1 < nch)
            LOAD_STAGE((i + STAGES - 1) % STAGES, k_beg + (i + STAGES - 1) * BK);
        asm volatile("cp.async.commit_group;" ::: "memory");

        const int s = i % STAGES;
        const float* As = sm + s * A_STAGE_FL;
        const float* Bs = sm + B_BASE_FL + s * B_STAGE_FL;

        const float* apb = As + (wm + qrow) * AP + qcol;
        const float* bpb = Bs + qcol * BP + wn + qrow;

        uint32_t af[2][4][4], bf[2][8][2];
        // Prefetch kstep 0 fragments (A and B).
#pragma unroll
        for (int mt = 0; mt < 4; mt++) {
            const float* ap = apb + mt * 16 * AP;
            af[0][mt][0] = ld_tf32(ap);
            af[0][mt][1] = ld_tf32(ap + 8 * AP);
            af[0][mt][2] = ld_tf32(ap + 4);
            af[0][mt][3] = ld_tf32(ap + 8 * AP + 4);
        }
#pragma unroll
        for (int nt = 0; nt < 8; nt++) {
            const float* bp = bpb + nt * 8;
            bf[0][nt][0] = ld_tf32(bp);
            bf[0][nt][1] = ld_tf32(bp + 4 * BP);
        }

#pragma unroll
        for (int ks = 0; ks < BK / 8; ks++) {
            const int cur = ks & 1;
            const int nxt = cur ^ 1;
            // Prefetch kstep ks+1 fragments before issuing MMAs for ks.
            if (ks < BK / 8 - 1) {
#pragma unroll
                for (int mt = 0; mt < 4; mt++) {
                    const float* ap = apb + mt * 16 * AP + (ks + 1) * 8;
                    af[nxt][mt][0] = ld_tf32(ap);
                    af[nxt][mt][1] = ld_tf32(ap + 8 * AP);
                    af[nxt][mt][2] = ld_tf32(ap + 4);
                    af[nxt][mt][3] = ld_tf32(ap + 8 * AP + 4);
                }
#pragma unroll
                for (int nt = 0; nt < 8; nt++) {
                    const float* bp = bpb + (ks + 1) * 8 * BP + nt * 8;
                    bf[nxt][nt][0] = ld_tf32(bp);
                    bf[nxt][nt][1] = ld_tf32(bp + 4 * BP);
                }
            }
#pragma unroll
            for (int mt = 0; mt < 4; mt++)
#pragma unroll
                for (int nt = 0; nt < 8; nt++) {
                    asm volatile(
                        "mma.sync.aligned.m16n8k8.row.col.f32.tf32.tf32.f32 "
                        "{%0,%1,%2,%3}, {%4,%5,%6,%7}, {%8,%9}, {%0,%1,%2,%3};"
                        : "+f"(acc[mt][nt][0]), "+f"(acc[mt][nt][1]),
                          "+f"(acc[mt][nt][2]), "+f"(acc[mt][nt][3])
                        : "r"(af[cur][mt][0]), "r"(af[cur][mt][1]),
                          "r"(af[cur][mt][2]), "r"(af[cur][mt][3]),
                          "r"(bf[cur][nt][0]), "r"(bf[cur][nt][1]));
                }
        }
        __syncthreads();
    }

    // ---- Epilogue ----
    if (split) {
        // Split pieces come only from strictly-above-diagonal tiles.
#pragma unroll
        for (int mt = 0; mt < 4; mt++) {
            const int r_lo = row0 + wm + mt * 16 + qrow;
            float* crow_lo = C + (size_t)r_lo * N_DIM;
            float* crow_hi = crow_lo + (size_t)8 * N_DIM;
#pragma unroll
            for (int nt = 0; nt < 8; nt++) {
                const int gc = col0 + wn + nt * 8 + qcol * 2;
                red_add_f32(crow_lo + gc,     acc[mt][nt][0]);
                red_add_f32(crow_lo + gc + 1, acc[mt][nt][1]);
                red_add_f32(crow_hi + gc,     acc[mt][nt][2]);
                red_add_f32(crow_hi + gc + 1, acc[mt][nt][3]);
            }
        }
    } else {
#pragma unroll
        for (int mt = 0; mt < 4; mt++) {
            const int r_lo = row0 + wm + mt * 16 + qrow;
            const int r_hi = r_lo + 8;
            float* crow_lo = C + (size_t)r_lo * N_DIM;
            float* crow_hi = C + (size_t)r_hi * N_DIM;
#pragma unroll
            for (int nt = 0; nt < 8; nt++) {
                const int gc = col0 + wn + nt * 8 + qcol * 2;
                float2 v0, v1;
                v0.x = (gc + 0 >= r_lo) ? acc[mt][nt][0] : 0.0f;
                v0.y = (gc + 1 >= r_lo) ? acc[mt][nt][1] : 0.0f;
                v1.x = (gc + 0 >= r_hi) ? acc[mt][nt][2] : 0.0f;
                v1.y = (gc + 1 >= r_hi) ? acc[mt][nt][3] : 0.0f;
                *reinterpret_cast<float2*>(crow_lo + gc) = v0;
                *reinterpret_cast<float2*>(crow_hi + gc) = v1;
            }
        }
    }
}

extern "C" void kernel_launch(void* const* d_in, const int* in_sizes, int n_in,
                              void* d_out, int out_size) {
    const float* A = (const float*)d_in[0];
    const float* B = (const float*)d_in[1];
    float* C = (float*)d_out;

    // Schedule: 128x256 upper tiles (it <= 2*jt+1), longest K first,
    // tiles with K-length > SPLIT_L*128 split into even pieces.
    static int4 h_sched[MAX_PIECES];
    int cnt = 0;
    for (int L = 32; L >= 1; L--) {               // K-length in 128-chunks
        for (int jt = 0; jt < 16; jt++) {
            const int it = 2 * jt + 2 - L;
            if (it < 0 || it > 2 * jt + 1) continue;
            const int pieces = (L + SPLIT_L - 1) / SPLIT_L;
            for (int q = 0; q < pieces; q++) {
                const int c0 = it + (q * L) / pieces;
                const int c1 = it + ((q + 1) * L) / pieces;
                h_sched[cnt].x = it;
                h_sched[cnt].y = jt;
                h_sched[cnt].z = c0 * 128;
                h_sched[cnt].w = c1 * 128;
                cnt++;
            }
        }
    }

    cudaFuncSetAttribute(triu_gemm_tf32mma_kernel,
                         cudaFuncAttributeMaxDynamicSharedMemorySize,
                         SMEM_FL * sizeof(float));

    cudaMemcpyToSymbolAsync(g_sched, h_sched, cnt * sizeof(int4), 0,
                            cudaMemcpyHostToDevice, 0);
    cudaMemsetAsync(d_out, 0, (size_t)N_DIM * N_DIM * sizeof(float), 0);
    triu_gemm_tf32mma_kernel<<<cnt, NTHREADS, SMEM_FL * sizeof(float)>>>(A, B, C);
}

// round 7
// speedup vs baseline: 1.2894x; 1.1671x over previous
#include <cuda_runtime.h>
#include <cuda_fp16.h>
#include <cstdint>

// C = triu(A @ B), A,B upper-triangular fp32, N=4096.
// Round 7: fp16 mma.sync m16n8k16 (halves tensor-pipe instruction count vs
// tf32 k8; same 10-bit mantissa => same precision class).
//   Pre-pass: A -> g_Ah (half, [m][k]); B -> g_Bt (half, transposed [n][k]).
//   GEMM: 128x256 tiles / 64x64 warp tiles, BK=64, 3-stage cp.async (162KB),
//   fragments are raw LDS.32 half2 (no cvt in loop), A+B frag double-buffer,
//   split-K (atomics) for K>1024, longest-K-first schedule.

#define N_DIM 4096
#define BM 128
#define BN 256
#define BK 64
#define STAGES 3
#define NTHREADS 256
#define SPLIT_L 8

#define APh 72   // A smem pitch (halfs): frag bank = (4*qrow+qcol)%32, distinct
#define BPh 72   // B^T smem pitch (halfs): same pattern
#define A_STAGE_H (BM * APh)                 // 9216 halfs (18432 B)
#define B_STAGE_H (BN * BPh)                 // 18432 halfs (36864 B)
#define B_BASE_H  (STAGES * A_STAGE_H)       // 27648
#define SMEM_H    (B_BASE_H + STAGES * B_STAGE_H)  // 82944 halfs = 165888 B

#define MAX_PIECES 1024
__device__ int4 g_sched[MAX_PIECES];
__device__ __half g_Ah[(size_t)N_DIM * N_DIM];   // A, half, row-major [m][k]
__device__ __half g_Bt[(size_t)N_DIM * N_DIM];   // B^T, half, [n][k]

__device__ __forceinline__ uint32_t smem_u32(const void* p) {
    uint32_t a;
    asm("{ .reg .u64 t; cvta.to.shared.u64 t, %1; cvt.u32.u64 %0, t; }" : "=r"(a) : "l"(p));
    return a;
}
__device__ __forceinline__ void cp_async16(uint32_t dst, const void* src) {
    asm volatile("cp.async.cg.shared.global [%0], [%1], 16;" :: "r"(dst), "l"(src));
}
__device__ __forceinline__ uint32_t ld_s32(const __half* p) {
    return *reinterpret_cast<const uint32_t*>(p);
}
__device__ __forceinline__ void red_add_f32(float* p, float v) {
    asm volatile("red.global.add.f32 [%0], %1;" :: "l"(p), "f"(v) : "memory");
}

// ---------------- Pre-pass: convert / transpose to half ----------------

__global__ __launch_bounds__(256) void conv_a_kernel(const float* __restrict__ A) {
    const size_t i = (size_t)(blockIdx.x * 256 + threadIdx.x) * 8;
    float4 v0 = *reinterpret_cast<const float4*>(A + i);
    float4 v1 = *reinterpret_cast<const float4*>(A + i + 4);
    __half2 h[4];
    h[0] = __floats2half2_rn(v0.x, v0.y);
    h[1] = __floats2half2_rn(v0.z, v0.w);
    h[2] = __floats2half2_rn(v1.x, v1.y);
    h[3] = __floats2half2_rn(v1.z, v1.w);
    *reinterpret_cast<uint4*>(g_Ah + i) = *reinterpret_cast<uint4*>(h);
}

// g_Bt[n][k] = half(B[k][n])
__global__ __launch_bounds__(256) void transpose_b_kernel(const float* __restrict__ B) {
    __shared__ float t[32][33];
    const int bx = blockIdx.x * 32;  // n
    const int by = blockIdx.y * 32;  // k
    const int x = threadIdx.x;
#pragma unroll
    for (int i = threadIdx.y; i < 32; i += 8)
        t[i][x] = B[(size_t)(by + i) * N_DIM + bx + x];
    __syncthreads();
#pragma unroll
    for (int i = threadIdx.y; i < 32; i += 8)
        g_Bt[(size_t)(bx + i) * N_DIM + by + x] = __float2half_rn(t[x][i]);
}

// ---------------- Main GEMM ----------------

__global__ __launch_bounds__(NTHREADS, 1)
void triu_gemm_f16mma_kernel(float* __restrict__ C)
{
    extern __shared__ __half smh[];
    const uint32_t smb = smem_u32(smh);

    const int tid  = threadIdx.x;
    const int wid  = tid >> 5;
    const int lane = tid & 31;
    const int qrow = lane >> 2;
    const int qcol = lane & 3;

    const int4 e  = g_sched[blockIdx.x];
    const int it    = e.x;
    const int jt    = e.y;
    const int k_beg = e.z;
    const int nch   = (e.w - e.z) / BK;
    const int split = ((2 * jt + 2 - it) > SPLIT_L);

    const int row0 = it * BM;
    const int col0 = jt * BN;

    const int wm = (wid & 1) * 64;
    const int wn = (wid >> 1) * 64;

    float acc[4][8][4];
#pragma unroll
    for (int i = 0; i < 4; i++)
#pragma unroll
        for (int j = 0; j < 8; j++)
#pragma unroll
            for (int r = 0; r < 4; r++) acc[i][j][r] = 0.0f;

    // cp.async thread mapping: rows of 64 halfs = 8 x 16B segs.
    const int arow = tid >> 3;   // 0..31 (+32 per rep, A: 4 reps, B: 8 reps)
    const int aseg = tid & 7;

    const __half* Ag = g_Ah + (size_t)(row0 + arow) * N_DIM + aseg * 8;
    const __half* Bg = g_Bt + (size_t)(col0 + arow) * N_DIM + aseg * 8;

#define LOAD_STAGE(s, kc)                                                        \
    do {                                                                         \
        const uint32_t abase = smb + ((s) * A_STAGE_H) * 2;                      \
        const uint32_t bbase = smb + (B_BASE_H + (s) * B_STAGE_H) * 2;           \
        _Pragma("unroll")                                                        \
        for (int r = 0; r < 4; r++)                                             \
            cp_async16(abase + ((arow + r * 32) * APh + aseg * 8) * 2,           \
                       Ag + (size_t)(r * 32) * N_DIM + (kc));                    \
        _Pragma("unroll")                                                        \
        for (int r = 0; r < 8; r++)                                             \
            cp_async16(bbase + ((arow + r * 32) * BPh + aseg * 8) * 2,           \
                       Bg + (size_t)(r * 32) * N_DIM + (kc));                    \
    } while (0)

#pragma unroll
    for (int s = 0; s < STAGES - 1; s++) {
        LOAD_STAGE(s, k_beg + s * BK);
        asm volatile("cp.async.commit_group;" ::: "memory");
    }

    for (int i = 0; i < nch; i++) {
        asm volatile("cp.async.wait_group %0;" :: "n"(STAGES - 2) : "memory");
        __syncthreads();

        if (i + STAGES - 1 < nch)
            LOAD_STAGE((i + STAGES - 1) % STAGES, k_beg + (i + STAGES - 1) * BK);
        asm volatile("cp.async.commit_group;" ::: "memory");

        const int s = i % STAGES;
        const __half* As = smh + s * A_STAGE_H;
        const __half* Bs = smh + B_BASE_H + s * B_STAGE_H;

        const __half* apb = As + (wm + qrow) * APh + 2 * qcol;
        const __half* bpb = Bs + (wn + qrow) * BPh + 2 * qcol;

        uint32_t af[2][4][4], bf[2][8][2];
        // Prefetch kstep 0 fragments.
#pragma unroll
        for (int mt = 0; mt < 4; mt++) {
            const __half* ap = apb + mt * 16 * APh;
            af[0][mt][0] = ld_s32(ap);
            af[0][mt][1] = ld_s32(ap + 8 * APh);
            af[0][mt][2] = ld_s32(ap + 8);
            af[0][mt][3] = ld_s32(ap + 8 * APh + 8);
        }
#pragma unroll
        for (int nt = 0; nt < 8; nt++) {
            const __half* bp = bpb + nt * 8 * BPh;
            bf[0][nt][0] = ld_s32(bp);
            bf[0][nt][1] = ld_s32(bp + 8);
        }

#pragma unroll
        for (int ks = 0; ks < BK / 16; ks++) {
            const int cur = ks & 1;
            const int nxt = cur ^ 1;
            if (ks < BK / 16 - 1) {
#pragma unroll
                for (int mt = 0; mt < 4; mt++) {
                    const __half* ap = apb + mt * 16 * APh + (ks + 1) * 16;
                    af[nxt][mt][0] = ld_s32(ap);
                    af[nxt][mt][1] = ld_s32(ap + 8 * APh);
                    af[nxt][mt][2] = ld_s32(ap + 8);
                    af[nxt][mt][3] = ld_s32(ap + 8 * APh + 8);
                }
#pragma unroll
                for (int nt = 0; nt < 8; nt++) {
                    const __half* bp = bpb + nt * 8 * BPh + (ks + 1) * 16;
                    bf[nxt][nt][0] = ld_s32(bp);
                    bf[nxt][nt][1] = ld_s32(bp + 8);
                }
            }
#pragma unroll
            for (int mt = 0; mt < 4; mt++)
#pragma unroll
                for (int nt = 0; nt < 8; nt++) {
                    asm volatile(
                        "mma.sync.aligned.m16n8k16.row.col.f32.f16.f16.f32 "
                        "{%0,%1,%2,%3}, {%4,%5,%6,%7}, {%8,%9}, {%0,%1,%2,%3};"
                        : "+f"(acc[mt][nt][0]), "+f"(acc[mt][nt][1]),
                          "+f"(acc[mt][nt][2]), "+f"(acc[mt][nt][3])
                        : "r"(af[cur][mt][0]), "r"(af[cur][mt][1]),
                          "r"(af[cur][mt][2]), "r"(af[cur][mt][3]),
                          "r"(bf[cur][nt][0]), "r"(bf[cur][nt][1]));
                }
        }
        __syncthreads();
    }

    // ---- Epilogue ----
    if (split) {
#pragma unroll
        for (int mt = 0; mt < 4; mt++) {
            const int r_lo = row0 + wm + mt * 16 + qrow;
            float* crow_lo = C + (size_t)r_lo * N_DIM;
            float* crow_hi = crow_lo + (size_t)8 * N_DIM;
#pragma unroll
            for (int nt = 0; nt < 8; nt++) {
                const int gc = col0 + wn + nt * 8 + qcol * 2;
                red_add_f32(crow_lo + gc,     acc[mt][nt][0]);
                red_add_f32(crow_lo + gc + 1, acc[mt][nt][1]);
                red_add_f32(crow_hi + gc,     acc[mt][nt][2]);
                red_add_f32(crow_hi + gc + 1, acc[mt][nt][3]);
            }
        }
    } else {
#pragma unroll
        for (int mt = 0; mt < 4; mt++) {
            const int r_lo = row0 + wm + mt * 16 + qrow;
            const int r_hi = r_lo + 8;
            float* crow_lo = C + (size_t)r_lo * N_DIM;
            float* crow_hi = C + (size_t)r_hi * N_DIM;
#pragma unroll
            for (int nt = 0; nt < 8; nt++) {
                const int gc = col0 + wn + nt * 8 + qcol * 2;
                float2 v0, v1;
                v0.x = (gc + 0 >= r_lo) ? acc[mt][nt][0] : 0.0f;
                v0.y = (gc + 1 >= r_lo) ? acc[mt][nt][1] : 0.0f;
                v1.x = (gc + 0 >= r_hi) ? acc[mt][nt][2] : 0.0f;
                v1.y = (gc + 1 >= r_hi) ? acc[mt][nt][3] : 0.0f;
                *reinterpret_cast<float2*>(crow_lo + gc) = v0;
                *reinterpret_cast<float2*>(crow_hi + gc) = v1;
            }
        }
    }
}

extern "C" void kernel_launch(void* const* d_in, const int* in_sizes, int n_in,
                              void* d_out, int out_size) {
    const float* A = (const float*)d_in[0];
    const float* B = (const float*)d_in[1];
    float* C = (float*)d_out;

    // Schedule: 128x256 upper tiles (it <= 2*jt+1), longest K first,
    // tiles with K-length > SPLIT_L*128 split into even pieces.
    static int4 h_sched[MAX_PIECES];
    int cnt = 0;
    for (int L = 32; L >= 1; L--) {
        for (int jt = 0; jt < 16; jt++) {
            const int it = 2 * jt + 2 - L;
            if (it < 0 || it > 2 * jt + 1) continue;
            const int pieces = (L + SPLIT_L - 1) / SPLIT_L;
            for (int q = 0; q < pieces; q++) {
                const int c0 = it + (q * L) / pieces;
                const int c1 = it + ((q + 1) * L) / pieces;
                h_sched[cnt].x = it;
                h_sched[cnt].y = jt;
                h_sched[cnt].z = c0 * 128;
                h_sched[cnt].w = c1 * 128;
                cnt++;
            }
        }
    }

    cudaFuncSetAttribute(triu_gemm_f16mma_kernel,
                         cudaFuncAttributeMaxDynamicSharedMemorySize,
                         SMEM_H * 2);

    cudaMemcpyToSymbolAsync(g_sched, h_sched, cnt * sizeof(int4), 0,
                            cudaMemcpyHostToDevice, 0);
    cudaMemsetAsync(d_out, 0, (size_t)N_DIM * N_DIM * sizeof(float), 0);
    conv_a_kernel<<<(int)(((size_t)N_DIM * N_DIM) / (256 * 8)), 256>>>(A);
    transpose_b_kernel<<<dim3(N_DIM / 32, N_DIM / 32), dim3(32, 8)>>>(B);
    triu_gemm_f16mma_kernel<<<cnt, NTHREADS, SMEM_H * 2>>>(C);
}

// round 8
// speedup vs baseline: 1.5509x; 1.2028x over previous
#include <cuda_runtime.h>
#include <cuda_fp16.h>
#include <cstdint>

// C = triu(A @ B), A,B upper-triangular fp32, N=4096.
// Round 8: fp16 m16n8k16 + ldmatrix.x4 fragment loads (4x fewer LDS issue
// slots) + triangular pre-passes (skip zero tiles; device globals zero-init).

#define N_DIM 4096
#define BM 128
#define BN 256
#define BK 64
#define STAGES 3
#define NTHREADS 256
#define SPLIT_L 8

#define APh 72   // A smem pitch (halfs); 144B row stride -> LDSM conflict-free
#define BPh 72
#define A_STAGE_H (BM * APh)
#define B_STAGE_H (BN * BPh)
#define B_BASE_H  (STAGES * A_STAGE_H)
#define SMEM_H    (B_BASE_H + STAGES * B_STAGE_H)   // 82944 halfs = 165888 B

#define MAX_PIECES 1024
__device__ int4 g_sched[MAX_PIECES];
__device__ __half g_Ah[(size_t)N_DIM * N_DIM];   // A half [m][k]; zero-init
__device__ __half g_Bt[(size_t)N_DIM * N_DIM];   // B^T half [n][k]; zero-init

__device__ __forceinline__ uint32_t smem_u32(const void* p) {
    uint32_t a;
    asm("{ .reg .u64 t; cvta.to.shared.u64 t, %1; cvt.u32.u64 %0, t; }" : "=r"(a) : "l"(p));
    return a;
}
__device__ __forceinline__ void cp_async16(uint32_t dst, const void* src) {
    asm volatile("cp.async.cg.shared.global [%0], [%1], 16;" :: "r"(dst), "l"(src));
}
__device__ __forceinline__ void red_add_f32(float* p, float v) {
    asm volatile("red.global.add.f32 [%0], %1;" :: "l"(p), "f"(v) : "memory");
}
#define LDSM_X4(r0, r1, r2, r3, a)                                              \
    asm volatile("ldmatrix.sync.aligned.m8n8.x4.shared.b16 {%0,%1,%2,%3}, [%4];" \
                 : "=r"(r0), "=r"(r1), "=r"(r2), "=r"(r3) : "r"(a))

// ---------------- Pre-pass: triangular convert / transpose ----------------

// Row i of A: nonzeros only at k >= i. Convert k in [i & ~31, N).
__global__ __launch_bounds__(256) void conv_a_kernel(const float* __restrict__ A) {
    const int row = blockIdx.x;
    const int k0 = row & ~31;
    const float* src = A + (size_t)row * N_DIM;
    __half* dst = g_Ah + (size_t)row * N_DIM;
    for (int k = k0 + threadIdx.x * 4; k < N_DIM; k += 256 * 4) {
        float4 v = *reinterpret_cast<const float4*>(src + k);
        __half2 h0 = __floats2half2_rn(v.x, v.y);
        __half2 h1 = __floats2half2_rn(v.z, v.w);
        uint2 u;
        u.x = *reinterpret_cast<uint32_t*>(&h0);
        u.y = *reinterpret_cast<uint32_t*>(&h1);
        *reinterpret_cast<uint2*>(dst + k) = u;
    }
}

// g_Bt[n][k] = half(B[k][n]); nonzero only k <= n -> skip tiles k_blk > n_blk.
__global__ __launch_bounds__(256) void transpose_b_kernel(const float* __restrict__ B) {
    const int bx = blockIdx.x * 32;  // n block
    const int by = blockIdx.y * 32;  // k block
    if (by > bx) return;             // entirely zero region
    __shared__ float t[32][33];
    const int x = threadIdx.x & 31;
    const int y0 = threadIdx.x >> 5;
#pragma unroll
    for (int i = y0; i < 32; i += 8)
        t[i][x] = B[(size_t)(by + i) * N_DIM + bx + x];
    __syncthreads();
#pragma unroll
    for (int i = y0; i < 32; i += 8)
        g_Bt[(size_t)(bx + i) * N_DIM + by + x] = __float2half_rn(t[x][i]);
}

// ---------------- Main GEMM ----------------

__global__ __launch_bounds__(NTHREADS, 1)
void triu_gemm_f16mma_kernel(float* __restrict__ C)
{
    extern __shared__ __half smh[];
    const uint32_t smb = smem_u32(smh);

    const int tid  = threadIdx.x;
    const int wid  = tid >> 5;
    const int lane = tid & 31;
    const int qrow = lane >> 2;
    const int qcol = lane & 3;

    const int4 e  = g_sched[blockIdx.x];
    const int it    = e.x;
    const int jt    = e.y;
    const int k_beg = e.z;
    const int nch   = (e.w - e.z) / BK;
    const int split = ((2 * jt + 2 - it) > SPLIT_L);

    const int row0 = it * BM;
    const int col0 = jt * BN;

    const int wm = (wid & 1) * 64;
    const int wn = (wid >> 1) * 64;

    float acc[4][8][4];
#pragma unroll
    for (int i = 0; i < 4; i++)
#pragma unroll
        for (int j = 0; j < 8; j++)
#pragma unroll
            for (int r = 0; r < 4; r++) acc[i][j][r] = 0.0f;

    // cp.async mapping: rows of 64 halfs = 8 x 16B segs.
    const int arow = tid >> 3;
    const int aseg = tid & 7;

    const __half* Ag = g_Ah + (size_t)(row0 + arow) * N_DIM + aseg * 8;
    const __half* Bg = g_Bt + (size_t)(col0 + arow) * N_DIM + aseg * 8;

#define LOAD_STAGE(s, kc)                                                        \
    do {                                                                         \
        const uint32_t abase = smb + ((s) * A_STAGE_H) * 2;                      \
        const uint32_t bbase = smb + (B_BASE_H + (s) * B_STAGE_H) * 2;           \
        _Pragma("unroll")                                                        \
        for (int r = 0; r < 4; r++)                                             \
            cp_async16(abase + ((arow + r * 32) * APh + aseg * 8) * 2,           \
                       Ag + (size_t)(r * 32) * N_DIM + (kc));                    \
        _Pragma("unroll")                                                        \
        for (int r = 0; r < 8; r++)                                             \
            cp_async16(bbase + ((arow + r * 32) * BPh + aseg * 8) * 2,           \
                       Bg + (size_t)(r * 32) * N_DIM + (kc));                    \
    } while (0)

    // Per-lane LDSM base offsets (halfs -> bytes at use).
    // A x4: matrices {m0-7,k0-7},{m8-15,k0-7},{m0-7,k8-15},{m8-15,k8-15}
    const uint32_t a_lane =
        ((wm + ((lane >> 3) & 1) * 8 + (lane & 7)) * APh + (lane >> 4) * 8) * 2;
    // B x4 (per pair p): {n0-7,k0-7},{n0-7,k8-15},{n8-15,k0-7},{n8-15,k8-15}
    const uint32_t b_lane =
        ((wn + (lane >> 4) * 8 + (lane & 7)) * BPh + ((lane >> 3) & 1) * 8) * 2;

#pragma unroll
    for (int s = 0; s < STAGES - 1; s++) {
        LOAD_STAGE(s, k_beg + s * BK);
        asm volatile("cp.async.commit_group;" ::: "memory");
    }

    for (int i = 0; i < nch; i++) {
        asm volatile("cp.async.wait_group %0;" :: "n"(STAGES - 2) : "memory");
        __syncthreads();

        if (i + STAGES - 1 < nch)
            LOAD_STAGE((i + STAGES - 1) % STAGES, k_beg + (i + STAGES - 1) * BK);
        asm volatile("cp.async.commit_group;" ::: "memory");

        const int s = i % STAGES;
        const uint32_t a_base = smb + (s * A_STAGE_H) * 2 + a_lane;
        const uint32_t b_base = smb + (B_BASE_H + s * B_STAGE_H) * 2 + b_lane;

        uint32_t af[2][4][4], bf[2][8][2];
        // Prefetch kstep 0.
#pragma unroll
        for (int mt = 0; mt < 4; mt++)
            LDSM_X4(af[0][mt][0], af[0][mt][1], af[0][mt][2], af[0][mt][3],
                    a_base + (mt * 16 * APh) * 2);
#pragma unroll
        for (int p = 0; p < 4; p++)
            LDSM_X4(bf[0][2 * p][0], bf[0][2 * p][1],
                    bf[0][2 * p + 1][0], bf[0][2 * p + 1][1],
                    b_base + (p * 16 * BPh) * 2);

#pragma unroll
        for (int ks = 0; ks < BK / 16; ks++) {
            const int cur = ks & 1;
            const int nxt = cur ^ 1;
            if (ks < BK / 16 - 1) {
                const uint32_t ko = ((ks + 1) * 16) * 2;
#pragma unroll
                for (int mt = 0; mt < 4; mt++)
                    LDSM_X4(af[nxt][mt][0], af[nxt][mt][1],
                            af[nxt][mt][2], af[nxt][mt][3],
                            a_base + (mt * 16 * APh) * 2 + ko);
#pragma unroll
                for (int p = 0; p < 4; p++)
                    LDSM_X4(bf[nxt][2 * p][0], bf[nxt][2 * p][1],
                            bf[nxt][2 * p + 1][0], bf[nxt][2 * p + 1][1],
                            b_base + (p * 16 * BPh) * 2 + ko);
            }
#pragma unroll
            for (int mt = 0; mt < 4; mt++)
#pragma unroll
                for (int nt = 0; nt < 8; nt++) {
                    asm volatile(
                        "mma.sync.aligned.m16n8k16.row.col.f32.f16.f16.f32 "
                        "{%0,%1,%2,%3}, {%4,%5,%6,%7}, {%8,%9}, {%0,%1,%2,%3};"
                        : "+f"(acc[mt][nt][0]), "+f"(acc[mt][nt][1]),
                          "+f"(acc[mt][nt][2]), "+f"(acc[mt][nt][3])
                        : "r"(af[cur][mt][0]), "r"(af[cur][mt][1]),
                          "r"(af[cur][mt][2]), "r"(af[cur][mt][3]),
                          "r"(bf[cur][nt][0]), "r"(bf[cur][nt][1]));
                }
        }
        __syncthreads();
    }

    // ---- Epilogue ----
    if (split) {
#pragma unroll
        for (int mt = 0; mt < 4; mt++) {
            const int r_lo = row0 + wm + mt * 16 + qrow;
            float* crow_lo = C + (size_t)r_lo * N_DIM;
            float* crow_hi = crow_lo + (size_t)8 * N_DIM;
#pragma unroll
            for (int nt = 0; nt < 8; nt++) {
                const int gc = col0 + wn + nt * 8 + qcol * 2;
                red_add_f32(crow_lo + gc,     acc[mt][nt][0]);
                red_add_f32(crow_lo + gc + 1, acc[mt][nt][1]);
                red_add_f32(crow_hi + gc,     acc[mt][nt][2]);
                red_add_f32(crow_hi + gc + 1, acc[mt][nt][3]);
            }
        }
    } else {
#pragma unroll
        for (int mt = 0; mt < 4; mt++) {
            const int r_lo = row0 + wm + mt * 16 + qrow;
            const int r_hi = r_lo + 8;
            float* crow_lo = C + (size_t)r_lo * N_DIM;
            float* crow_hi = C + (size_t)r_hi * N_DIM;
#pragma unroll
            for (int nt = 0; nt < 8; nt++) {
                const int gc = col0 + wn + nt * 8 + qcol * 2;
                float2 v0, v1;
                v0.x = (gc + 0 >= r_lo) ? acc[mt][nt][0] : 0.0f;
                v0.y = (gc + 1 >= r_lo) ? acc[mt][nt][1] : 0.0f;
                v1.x = (gc + 0 >= r_hi) ? acc[mt][nt][2] : 0.0f;
                v1.y = (gc + 1 >= r_hi) ? acc[mt][nt][3] : 0.0f;
                *reinterpret_cast<float2*>(crow_lo + gc) = v0;
                *reinterpret_cast<float2*>(crow_hi + gc) = v1;
            }
        }
    }
}

extern "C" void kernel_launch(void* const* d_in, const int* in_sizes, int n_in,
                              void* d_out, int out_size) {
    const float* A = (const float*)d_in[0];
    const float* B = (const float*)d_in[1];
    float* C = (float*)d_out;

    static int4 h_sched[MAX_PIECES];
    int cnt = 0;
    for (int L = 32; L >= 1; L--) {
        for (int jt = 0; jt < 16; jt++) {
            const int it = 2 * jt + 2 - L;
            if (it < 0 || it > 2 * jt + 1) continue;
            const int pieces = (L + SPLIT_L - 1) / SPLIT_L;
            for (int q = 0; q < pieces; q++) {
                const int c0 = it + (q * L) / pieces;
                const int c1 = it + ((q + 1) * L) / pieces;
                h_sched[cnt].x = it;
                h_sched[cnt].y = jt;
                h_sched[cnt].z = c0 * 128;
                h_sched[cnt].w = c1 * 128;
                cnt++;
            }
        }
    }

    cudaFuncSetAttribute(triu_gemm_f16mma_kernel,
                         cudaFuncAttributeMaxDynamicSharedMemorySize, SMEM_H * 2);

    cudaMemcpyToSymbolAsync(g_sched, h_sched, cnt * sizeof(int4), 0,
                            cudaMemcpyHostToDevice, 0);
    cudaMemsetAsync(d_out, 0, (size_t)N_DIM * N_DIM * sizeof(float), 0);
    conv_a_kernel<<<N_DIM, 256>>>(A);
    transpose_b_kernel<<<dim3(N_DIM / 32, N_DIM / 32), 256>>>(B);
    triu_gemm_f16mma_kernel<<<cnt, NTHREADS, SMEM_H * 2>>>(C);
}

// round 10
// speedup vs baseline: 1.5724x; 1.0138x over previous
#include <cuda_runtime.h>
#include <cuda_fp16.h>
#include <cstdint>

// C = triu(A @ B), A,B upper-triangular fp32, N=4096.
// Round 10: fp16 m16n8k16 + ldmatrix, fused triangular pre-pass, 4-stage
// cp.async pipeline. Fixes R9's OOB: prologue loads guarded for short
// split-K pieces (nch can be 2 < STAGES-1), empty commit_groups keep the
// wait_group accounting exact.

#define N_DIM 4096
#define BM 128
#define BN 256
#define BK 64
#define STAGES 4
#define NTHREADS 256
#define SPLIT_L 8

#define APh 72   // A smem pitch (halfs); LDSM conflict-free
#define BPh 72
#define A_STAGE_H (BM * APh)                       // 9216
#define B_STAGE_H (BN * BPh)                       // 18432
#define B_BASE_H  (STAGES * A_STAGE_H)             // 36864
#define SMEM_H    (B_BASE_H + STAGES * B_STAGE_H)  // 110592 halfs = 221184 B

#define MAX_PIECES 1024
__device__ int4 g_sched[MAX_PIECES];
__device__ __half g_Ah[(size_t)N_DIM * N_DIM];   // A half [m][k]; zero-init
__device__ __half g_Bt[(size_t)N_DIM * N_DIM];   // B^T half [n][k]; zero-init

__device__ __forceinline__ uint32_t smem_u32(const void* p) {
    uint32_t a;
    asm("{ .reg .u64 t; cvta.to.shared.u64 t, %1; cvt.u32.u64 %0, t; }" : "=r"(a) : "l"(p));
    return a;
}
__device__ __forceinline__ void cp_async16(uint32_t dst, const void* src) {
    asm volatile("cp.async.cg.shared.global [%0], [%1], 16;" :: "r"(dst), "l"(src));
}
__device__ __forceinline__ void red_add_f32(float* p, float v) {
    asm volatile("red.global.add.f32 [%0], %1;" :: "l"(p), "f"(v) : "memory");
}
#define LDSM_X4(r0, r1, r2, r3, a)                                              \
    asm volatile("ldmatrix.sync.aligned.m8n8.x4.shared.b16 {%0,%1,%2,%3}, [%4];" \
                 : "=r"(r0), "=r"(r1), "=r"(r2), "=r"(r3) : "r"(a))

// ---------------- Fused pre-pass ----------------
// Blocks [0, N_DIM): convert A row (k >= row only; rest stays zero-init).
// Blocks [N_DIM, N_DIM + 128*128): B^T 32x32 tile (by > bx -> zero, skip).
__global__ __launch_bounds__(256) void prep_kernel(const float* __restrict__ A,
                                                   const float* __restrict__ B) {
    const int b = blockIdx.x;
    if (b < N_DIM) {
        const int row = b;
        const int k0 = row & ~31;
        const float* src = A + (size_t)row * N_DIM;
        __half* dst = g_Ah + (size_t)row * N_DIM;
        for (int k = k0 + threadIdx.x * 4; k < N_DIM; k += 256 * 4) {
            float4 v = *reinterpret_cast<const float4*>(src + k);
            __half2 h0 = __floats2half2_rn(v.x, v.y);
            __half2 h1 = __floats2half2_rn(v.z, v.w);
            uint2 u;
            u.x = *reinterpret_cast<uint32_t*>(&h0);
            u.y = *reinterpret_cast<uint32_t*>(&h1);
            *reinterpret_cast<uint2*>(dst + k) = u;
        }
    } else {
        const int t = b - N_DIM;
        const int bx = (t & 127) * 32;   // n block
        const int by = (t >> 7) * 32;    // k block
        if (by > bx) return;             // zero region of B
        __shared__ float tt[32][33];
        const int x = threadIdx.x & 31;
        const int y0 = threadIdx.x >> 5;
#pragma unroll
        for (int i = y0; i < 32; i += 8)
            tt[i][x] = B[(size_t)(by + i) * N_DIM + bx + x];
        __syncthreads();
#pragma unroll
        for (int i = y0; i < 32; i += 8)
            g_Bt[(size_t)(bx + i) * N_DIM + by + x] = __float2half_rn(tt[x][i]);
    }
}

// ---------------- Main GEMM ----------------

__global__ __launch_bounds__(NTHREADS, 1)
void triu_gemm_f16mma_kernel(float* __restrict__ C)
{
    extern __shared__ __half smh[];
    const uint32_t smb = smem_u32(smh);

    const int tid  = threadIdx.x;
    const int wid  = tid >> 5;
    const int lane = tid & 31;
    const int qrow = lane >> 2;
    const int qcol = lane & 3;

    const int4 e  = g_sched[blockIdx.x];
    const int it    = e.x;
    const int jt    = e.y;
    const int k_beg = e.z;
    const int nch   = (e.w - e.z) / BK;
    const int split = ((2 * jt + 2 - it) > SPLIT_L);

    const int row0 = it * BM;
    const int col0 = jt * BN;

    const int wm = (wid & 1) * 64;
    const int wn = (wid >> 1) * 64;

    float acc[4][8][4];
#pragma unroll
    for (int i = 0; i < 4; i++)
#pragma unroll
        for (int j = 0; j < 8; j++)
#pragma unroll
            for (int r = 0; r < 4; r++) acc[i][j][r] = 0.0f;

    const int arow = tid >> 3;
    const int aseg = tid & 7;

    const __half* Ag = g_Ah + (size_t)(row0 + arow) * N_DIM + aseg * 8;
    const __half* Bg = g_Bt + (size_t)(col0 + arow) * N_DIM + aseg * 8;

#define LOAD_STAGE(s, kc)                                                        \
    do {                                                                         \
        const uint32_t abase = smb + ((s) * A_STAGE_H) * 2;                      \
        const uint32_t bbase = smb + (B_BASE_H + (s) * B_STAGE_H) * 2;           \
        _Pragma("unroll")                                                        \
        for (int r = 0; r < 4; r++)                                             \
            cp_async16(abase + ((arow + r * 32) * APh + aseg * 8) * 2,           \
                       Ag + (size_t)(r * 32) * N_DIM + (kc));                    \
        _Pragma("unroll")                                                        \
        for (int r = 0; r < 8; r++)                                             \
            cp_async16(bbase + ((arow + r * 32) * BPh + aseg * 8) * 2,           \
                       Bg + (size_t)(r * 32) * N_DIM + (kc));                    \
    } while (0)

    const uint32_t a_lane =
        ((wm + ((lane >> 3) & 1) * 8 + (lane & 7)) * APh + (lane >> 4) * 8) * 2;
    const uint32_t b_lane =
        ((wn + (lane >> 4) * 8 + (lane & 7)) * BPh + ((lane >> 3) & 1) * 8) * 2;

    // Prologue: guarded — short split-K pieces can have nch < STAGES-1.
#pragma unroll
    for (int s = 0; s < STAGES - 1; s++) {
        if (s < nch) LOAD_STAGE(s, k_beg + s * BK);
        asm volatile("cp.async.commit_group;" ::: "memory");
    }

    for (int i = 0; i < nch; i++) {
        asm volatile("cp.async.wait_group %0;" :: "n"(STAGES - 2) : "memory");
        __syncthreads();

        if (i + STAGES - 1 < nch)
            LOAD_STAGE((i + STAGES - 1) % STAGES, k_beg + (i + STAGES - 1) * BK);
        asm volatile("cp.async.commit_group;" ::: "memory");

        const int s = i % STAGES;
        const uint32_t a_base = smb + (s * A_STAGE_H) * 2 + a_lane;
        const uint32_t b_base = smb + (B_BASE_H + s * B_STAGE_H) * 2 + b_lane;

        uint32_t af[2][4][4], bf[2][8][2];
#pragma unroll
        for (int mt = 0; mt < 4; mt++)
            LDSM_X4(af[0][mt][0], af[0][mt][1], af[0][mt][2], af[0][mt][3],
                    a_base + (mt * 16 * APh) * 2);
#pragma unroll
        for (int p = 0; p < 4; p++)
            LDSM_X4(bf[0][2 * p][0], bf[0][2 * p][1],
                    bf[0][2 * p + 1][0], bf[0][2 * p + 1][1],
                    b_base + (p * 16 * BPh) * 2);

#pragma unroll
        for (int ks = 0; ks < BK / 16; ks++) {
            const int cur = ks & 1;
            const int nxt = cur ^ 1;
            if (ks < BK / 16 - 1) {
                const uint32_t ko = ((ks + 1) * 16) * 2;
#pragma unroll
                for (int mt = 0; mt < 4; mt++)
                    LDSM_X4(af[nxt][mt][0], af[nxt][mt][1],
                            af[nxt][mt][2], af[nxt][mt][3],
                            a_base + (mt * 16 * APh) * 2 + ko);
#pragma unroll
                for (int p = 0; p < 4; p++)
                    LDSM_X4(bf[nxt][2 * p][0], bf[nxt][2 * p][1],
                            bf[nxt][2 * p + 1][0], bf[nxt][2 * p + 1][1],
                            b_base + (p * 16 * BPh) * 2 + ko);
            }
#pragma unroll
            for (int mt = 0; mt < 4; mt++)
#pragma unroll
                for (int nt = 0; nt < 8; nt++) {
                    asm volatile(
                        "mma.sync.aligned.m16n8k16.row.col.f32.f16.f16.f32 "
                        "{%0,%1,%2,%3}, {%4,%5,%6,%7}, {%8,%9}, {%0,%1,%2,%3};"
                        : "+f"(acc[mt][nt][0]), "+f"(acc[mt][nt][1]),
                          "+f"(acc[mt][nt][2]), "+f"(acc[mt][nt][3])
                        : "r"(af[cur][mt][0]), "r"(af[cur][mt][1]),
                          "r"(af[cur][mt][2]), "r"(af[cur][mt][3]),
                          "r"(bf[cur][nt][0]), "r"(bf[cur][nt][1]));
                }
        }
        __syncthreads();
    }

    // ---- Epilogue ----
    if (split) {
#pragma unroll
        for (int mt = 0; mt < 4; mt++) {
            const int r_lo = row0 + wm + mt * 16 + qrow;
            float* crow_lo = C + (size_t)r_lo * N_DIM;
            float* crow_hi = crow_lo + (size_t)8 * N_DIM;
#pragma unroll
            for (int nt = 0; nt < 8; nt++) {
                const int gc = col0 + wn + nt * 8 + qcol * 2;
                red_add_f32(crow_lo + gc,     acc[mt][nt][0]);
                red_add_f32(crow_lo + gc + 1, acc[mt][nt][1]);
                red_add_f32(crow_hi + gc,     acc[mt][nt][2]);
                red_add_f32(crow_hi + gc + 1, acc[mt][nt][3]);
            }
        }
    } else {
#pragma unroll
        for (int mt = 0; mt < 4; mt++) {
            const int r_lo = row0 + wm + mt * 16 + qrow;
            const int r_hi = r_lo + 8;
            float* crow_lo = C + (size_t)r_lo * N_DIM;
            float* crow_hi = C + (size_t)r_hi * N_DIM;
#pragma unroll
            for (int nt = 0; nt < 8; nt++) {
                const int gc = col0 + wn + nt * 8 + qcol * 2;
                float2 v0, v1;
                v0.x = (gc + 0 >= r_lo) ? acc[mt][nt][0] : 0.0f;
                v0.y = (gc + 1 >= r_lo) ? acc[mt][nt][1] : 0.0f;
                v1.x = (gc + 0 >= r_hi) ? acc[mt][nt][2] : 0.0f;
                v1.y = (gc + 1 >= r_hi) ? acc[mt][nt][3] : 0.0f;
                *reinterpret_cast<float2*>(crow_lo + gc) = v0;
                *reinterpret_cast<float2*>(crow_hi + gc) = v1;
            }
        }
    }
}

extern "C" void kernel_launch(void* const* d_in, const int* in_sizes, int n_in,
                              void* d_out, int out_size) {
    const float* A = (const float*)d_in[0];
    const float* B = (const float*)d_in[1];
    float* C = (float*)d_out;

    static int4 h_sched[MAX_PIECES];
    int cnt = 0;
    for (int L = 32; L >= 1; L--) {
        for (int jt = 0; jt < 16; jt++) {
            const int it = 2 * jt + 2 - L;
            if (it < 0 || it > 2 * jt + 1) continue;
            const int pieces = (L + SPLIT_L - 1) / SPLIT_L;
            for (int q = 0; q < pieces; q++) {
                const int c0 = it + (q * L) / pieces;
                const int c1 = it + ((q + 1) * L) / pieces;
                h_sched[cnt].x = it;
                h_sched[cnt].y = jt;
                h_sched[cnt].z = c0 * 128;
                h_sched[cnt].w = c1 * 128;
                cnt++;
            }
        }
    }

    cudaFuncSetAttribute(triu_gemm_f16mma_kernel,
                         cudaFuncAttributeMaxDynamicSharedMemorySize, SMEM_H * 2);

    cudaMemcpyToSymbolAsync(g_sched, h_sched, cnt * sizeof(int4), 0,
                            cudaMemcpyHostToDevice, 0);
    cudaMemsetAsync(d_out, 0, (size_t)N_DIM * N_DIM * sizeof(float), 0);
    prep_kernel<<<N_DIM + 128 * 128, 256>>>(A, B);
    triu_gemm_f16mma_kernel<<<cnt, NTHREADS, SMEM_H * 2>>>(C);
}

// round 11
// speedup vs baseline: 1.6436x; 1.0453x over previous
#include <cuda_runtime.h>
#include <cuda_fp16.h>
#include <cstdint>

// C = triu(A @ B), A,B upper-triangular fp32, N=4096.
// Round 11: fp16 m16n8k16 + ldmatrix GEMM at the legacy-HMMA rate wall;
// overhead pass: memset folded into prep (zero only lower/split C tiles),
// schedule decoded in-kernel (no memcpyToSymbol), one barrier per chunk.

#define N_DIM 4096
#define BM 128
#define BN 256
#define BK 64
#define STAGES 4
#define NTHREADS 256
#define SPLIT_L 8

#define APh 72
#define BPh 72
#define A_STAGE_H (BM * APh)
#define B_STAGE_H (BN * BPh)
#define B_BASE_H  (STAGES * A_STAGE_H)
#define SMEM_H    (B_BASE_H + STAGES * B_STAGE_H)  // 110592 halfs = 221184 B

__device__ __half g_Ah[(size_t)N_DIM * N_DIM];   // A half [m][k]; zero-init
__device__ __half g_Bt[(size_t)N_DIM * N_DIM];   // B^T half [n][k]; zero-init

__device__ __forceinline__ uint32_t smem_u32(const void* p) {
    uint32_t a;
    asm("{ .reg .u64 t; cvta.to.shared.u64 t, %1; cvt.u32.u64 %0, t; }" : "=r"(a) : "l"(p));
    return a;
}
__device__ __forceinline__ void cp_async16(uint32_t dst, const void* src) {
    asm volatile("cp.async.cg.shared.global [%0], [%1], 16;" :: "r"(dst), "l"(src));
}
__device__ __forceinline__ void red_add_f32(float* p, float v) {
    asm volatile("red.global.add.f32 [%0], %1;" :: "l"(p), "f"(v) : "memory");
}
#define LDSM_X4(r0, r1, r2, r3, a)                                              \
    asm volatile("ldmatrix.sync.aligned.m8n8.x4.shared.b16 {%0,%1,%2,%3}, [%4];" \
                 : "=r"(r0), "=r"(r1), "=r"(r2), "=r"(r3) : "r"(a))

// ---------------- Fused pre-pass + selective C zeroing ----------------
// blocks [0, 4096): convert A row (k >= row).
// blocks [4096, 4096+16384): B^T 32x32 tile (skip k_blk > n_blk).
// blocks [4096+16384, +2048): zero 32-row slabs of C tiles that are
//   lower-triangular or split-K targets (atomic accumulation needs 0-init).
#define PREP_A 4096
#define PREP_B (128 * 128)
#define PREP_Z (512 * 4)

__global__ __launch_bounds__(256) void prep_kernel(const float* __restrict__ A,
                                                   const float* __restrict__ B,
                                                   float* __restrict__ C) {
    const int b = blockIdx.x;
    if (b < PREP_A) {
        const int row = b;
        const int k0 = row & ~31;
        const float* src = A + (size_t)row * N_DIM;
        __half* dst = g_Ah + (size_t)row * N_DIM;
        for (int k = k0 + threadIdx.x * 4; k < N_DIM; k += 256 * 4) {
            float4 v = *reinterpret_cast<const float4*>(src + k);
            __half2 h0 = __floats2half2_rn(v.x, v.y);
            __half2 h1 = __floats2half2_rn(v.z, v.w);
            uint2 u;
            u.x = *reinterpret_cast<uint32_t*>(&h0);
            u.y = *reinterpret_cast<uint32_t*>(&h1);
            *reinterpret_cast<uint2*>(dst + k) = u;
        }
    } else if (b < PREP_A + PREP_B) {
        const int t = b - PREP_A;
        const int bx = (t & 127) * 32;   // n block
        const int by = (t >> 7) * 32;    // k block
        if (by > bx) return;             // zero region of B
        __shared__ float tt[32][33];
        const int x = threadIdx.x & 31;
        const int y0 = threadIdx.x >> 5;
#pragma unroll
        for (int i = y0; i < 32; i += 8)
            tt[i][x] = B[(size_t)(by + i) * N_DIM + bx + x];
        __syncthreads();
#pragma unroll
        for (int i = y0; i < 32; i += 8)
            g_Bt[(size_t)(bx + i) * N_DIM + by + x] = __float2half_rn(tt[x][i]);
    } else {
        const int z = b - PREP_A - PREP_B;       // [0, 2048)
        const int t = z >> 2;                    // tile id [0, 512)
        const int sub = z & 3;                   // 32-row slab
        const int it = t & 31;
        const int jt = t >> 5;
        const int L = 2 * jt + 2 - it;           // K-chunks if upper tile
        const bool upper = (it <= 2 * jt + 1);
        if (upper && L <= SPLIT_L) return;       // fully written by GEMM store
        const int row = it * BM + sub * 32 + (threadIdx.x >> 3);
        float4* dst = reinterpret_cast<float4*>(
            C + (size_t)row * N_DIM + jt * BN) + (threadIdx.x & 7);
        const float4 zv = make_float4(0.f, 0.f, 0.f, 0.f);
#pragma unroll
        for (int k = 0; k < 8; k++) dst[k * 8] = zv;
    }
}

// ---------------- Main GEMM ----------------

__global__ __launch_bounds__(NTHREADS, 1)
void triu_gemm_f16mma_kernel(float* __restrict__ C)
{
    extern __shared__ __half smh[];
    const uint32_t smb = smem_u32(smh);

    const int tid  = threadIdx.x;
    const int wid  = tid >> 5;
    const int lane = tid & 31;
    const int qrow = lane >> 2;
    const int qcol = lane & 3;

    // Decode blockIdx -> (it, jt, k range): L = K-length in 128-chunks,
    // enumerated L=32..1 (longest first); tiles with L > SPLIT_L split
    // into ceil(L/8) even pieces. Mirrors host grid-count loop exactly.
    int it, jt, k_beg, k_end, L;
    {
        int r = blockIdx.x;
        L = 32;
        int jt0, p, njt;
        for (;; L--) {
            jt0 = (L - 1) >> 1;
            p = (L + 7) >> 3;
            njt = 16 - jt0;
            if (r < njt * p) break;
            r -= njt * p;
        }
        jt = jt0 + r / p;
        const int q = r % p;
        it = 2 * jt + 2 - L;
        k_beg = (it + (q * L) / p) * 128;
        k_end = (it + ((q + 1) * L) / p) * 128;
    }
    const int nch = (k_end - k_beg) / BK;
    const int split = (L > SPLIT_L);

    const int row0 = it * BM;
    const int col0 = jt * BN;

    const int wm = (wid & 1) * 64;
    const int wn = (wid >> 1) * 64;

    float acc[4][8][4];
#pragma unroll
    for (int i = 0; i < 4; i++)
#pragma unroll
        for (int j = 0; j < 8; j++)
#pragma unroll
            for (int r2 = 0; r2 < 4; r2++) acc[i][j][r2] = 0.0f;

    const int arow = tid >> 3;
    const int aseg = tid & 7;

    const __half* Ag = g_Ah + (size_t)(row0 + arow) * N_DIM + aseg * 8;
    const __half* Bg = g_Bt + (size_t)(col0 + arow) * N_DIM + aseg * 8;

#define LOAD_STAGE(s, kc)                                                        \
    do {                                                                         \
        const uint32_t abase = smb + ((s) * A_STAGE_H) * 2;                      \
        const uint32_t bbase = smb + (B_BASE_H + (s) * B_STAGE_H) * 2;           \
        _Pragma("unroll")                                                        \
        for (int r1 = 0; r1 < 4; r1++)                                          \
            cp_async16(abase + ((arow + r1 * 32) * APh + aseg * 8) * 2,          \
                       Ag + (size_t)(r1 * 32) * N_DIM + (kc));                   \
        _Pragma("unroll")                                                        \
        for (int r1 = 0; r1 < 8; r1++)                                          \
            cp_async16(bbase + ((arow + r1 * 32) * BPh + aseg * 8) * 2,          \
                       Bg + (size_t)(r1 * 32) * N_DIM + (kc));                   \
    } while (0)

    const uint32_t a_lane =
        ((wm + ((lane >> 3) & 1) * 8 + (lane & 7)) * APh + (lane >> 4) * 8) * 2;
    const uint32_t b_lane =
        ((wn + (lane >> 4) * 8 + (lane & 7)) * BPh + ((lane >> 3) & 1) * 8) * 2;

    // Prologue (guarded: short pieces can have nch < STAGES-1).
#pragma unroll
    for (int s = 0; s < STAGES - 1; s++) {
        if (s < nch) LOAD_STAGE(s, k_beg + s * BK);
        asm volatile("cp.async.commit_group;" ::: "memory");
    }

    for (int i = 0; i < nch; i++) {
        asm volatile("cp.async.wait_group %0;" :: "n"(STAGES - 2) : "memory");
        __syncthreads();   // single barrier/chunk: orders stage-i compute of
                           // ALL warps before anyone reloads that slot below.

        if (i + STAGES - 1 < nch)
            LOAD_STAGE((i + STAGES - 1) % STAGES, k_beg + (i + STAGES - 1) * BK);
        asm volatile("cp.async.commit_group;" ::: "memory");

        const int s = i % STAGES;
        const uint32_t a_base = smb + (s * A_STAGE_H) * 2 + a_lane;
        const uint32_t b_base = smb + (B_BASE_H + s * B_STAGE_H) * 2 + b_lane;

        uint32_t af[2][4][4], bf[2][8][2];
#pragma unroll
        for (int mt = 0; mt < 4; mt++)
            LDSM_X4(af[0][mt][0], af[0][mt][1], af[0][mt][2], af[0][mt][3],
                    a_base + (mt * 16 * APh) * 2);
#pragma unroll
        for (int p = 0; p < 4; p++)
            LDSM_X4(bf[0][2 * p][0], bf[0][2 * p][1],
                    bf[0][2 * p + 1][0], bf[0][2 * p + 1][1],
                    b_base + (p * 16 * BPh) * 2);

#pragma unroll
        for (int ks = 0; ks < BK / 16; ks++) {
            const int cur = ks & 1;
            const int nxt = cur ^ 1;
            if (ks < BK / 16 - 1) {
                const uint32_t ko = ((ks + 1) * 16) * 2;
#pragma unroll
                for (int mt = 0; mt < 4; mt++)
                    LDSM_X4(af[nxt][mt][0], af[nxt][mt][1],
                            af[nxt][mt][2], af[nxt][mt][3],
                            a_base + (mt * 16 * APh) * 2 + ko);
#pragma unroll
                for (int p = 0; p < 4; p++)
                    LDSM_X4(bf[nxt][2 * p][0], bf[nxt][2 * p][1],
                            bf[nxt][2 * p + 1][0], bf[nxt][2 * p + 1][1],
                            b_base + (p * 16 * BPh) * 2 + ko);
            }
#pragma unroll
            for (int mt = 0; mt < 4; mt++)
#pragma unroll
                for (int nt = 0; nt < 8; nt++) {
                    asm volatile(
                        "mma.sync.aligned.m16n8k16.row.col.f32.f16.f16.f32 "
                        "{%0,%1,%2,%3}, {%4,%5,%6,%7}, {%8,%9}, {%0,%1,%2,%3};"
                        : "+f"(acc[mt][nt][0]), "+f"(acc[mt][nt][1]),
                          "+f"(acc[mt][nt][2]), "+f"(acc[mt][nt][3])
                        : "r"(af[cur][mt][0]), "r"(af[cur][mt][1]),
                          "r"(af[cur][mt][2]), "r"(af[cur][mt][3]),
                          "r"(bf[cur][nt][0]), "r"(bf[cur][nt][1]));
                }
        }
    }
    __syncthreads();

    // ---- Epilogue ----
    if (split) {
#pragma unroll
        for (int mt = 0; mt < 4; mt++) {
            const int r_lo = row0 + wm + mt * 16 + qrow;
            float* crow_lo = C + (size_t)r_lo * N_DIM;
            float* crow_hi = crow_lo + (size_t)8 * N_DIM;
#pragma unroll
            for (int nt = 0; nt < 8; nt++) {
                const int gc = col0 + wn + nt * 8 + qcol * 2;
                red_add_f32(crow_lo + gc,     acc[mt][nt][0]);
                red_add_f32(crow_lo + gc + 1, acc[mt][nt][1]);
                red_add_f32(crow_hi + gc,     acc[mt][nt][2]);
                red_add_f32(crow_hi + gc + 1, acc[mt][nt][3]);
            }
        }
    } else {
#pragma unroll
        for (int mt = 0; mt < 4; mt++) {
            const int r_lo = row0 + wm + mt * 16 + qrow;
            const int r_hi = r_lo + 8;
            float* crow_lo = C + (size_t)r_lo * N_DIM;
            float* crow_hi = C + (size_t)r_hi * N_DIM;
#pragma unroll
            for (int nt = 0; nt < 8; nt++) {
                const int gc = col0 + wn + nt * 8 + qcol * 2;
                float2 v0, v1;
                v0.x = (gc + 0 >= r_lo) ? acc[mt][nt][0] : 0.0f;
                v0.y = (gc + 1 >= r_lo) ? acc[mt][nt][1] : 0.0f;
                v1.x = (gc + 0 >= r_hi) ? acc[mt][nt][2] : 0.0f;
                v1.y = (gc + 1 >= r_hi) ? acc[mt][nt][3] : 0.0f;
                *reinterpret_cast<float2*>(crow_lo + gc) = v0;
                *reinterpret_cast<float2*>(crow_hi + gc) = v1;
            }
        }
    }
}

extern "C" void kernel_launch(void* const* d_in, const int* in_sizes, int n_in,
                              void* d_out, int out_size) {
    const float* A = (const float*)d_in[0];
    const float* B = (const float*)d_in[1];
    float* C = (float*)d_out;

    // Grid size = number of schedule pieces (same enumeration as device decode).
    int cnt = 0;
    for (int L = 32; L >= 1; L--) {
        const int jt0 = (L - 1) >> 1;
        const int p = (L + 7) >> 3;
        cnt += (16 - jt0) * p;
    }

    cudaFuncSetAttribute(triu_gemm_f16mma_kernel,
                         cudaFuncAttributeMaxDynamicSharedMemorySize, SMEM_H * 2);

    prep_kernel<<<PREP_A + PREP_B + PREP_Z, 256>>>(A, B, C);
    triu_gemm_f16mma_kernel<<<cnt, NTHREADS, SMEM_H * 2>>>(C);
}